// round 11
// baseline (speedup 1.0000x reference)
#include <cuda_runtime.h>
#include <cuda_fp16.h>
#include <math.h>

#define S_LEN   2048
#define BATCH   2
#define NHEAD   32
#define KVHEADS 8
#define HDIM    64
#define WIN     256
#define GROUP   4
#define QTILE   32
#define NC      64
#define QSTRIDE (NHEAD*HDIM)
#define KSTRIDE (KVHEADS*HDIM)
#define KROW    72
#define STAGE_HALVES (2*NC*KROW)
// Q staging (128*KROW=18KB) overlays the 2 stages (36KB). 3 CTAs/SM.
#define SMEM_BYTES   (2*STAGE_HALVES*2)

// 0.125 * log2(e): scores come out of QK^T in log2 domain
#define QSCALE 0.18033688011112042f

__device__ float g_cos[S_LEN * 32];
__device__ float g_sin[S_LEN * 32];

__device__ __align__(16) __half Khalf[(size_t)BATCH * KVHEADS * S_LEN * HDIM];
__device__ __align__(16) __half Vhalf[(size_t)BATCH * KVHEADS * S_LEN * HDIM];

__global__ void prep_kv_kernel(const float* __restrict__ K, const float* __restrict__ V) {
    int idx = blockIdx.x * blockDim.x + threadIdx.x;
    if (idx >= BATCH * S_LEN * KVHEADS * 32) return;
    int d  = idx & 31;
    int kh = (idx >> 5) & 7;
    int s  = (idx >> 8) & 2047;
    int b  = idx >> 19;

    float inv = exp2f((float)d * -0.4152410118923361f);   // 10000^(-d/32)
    float sn, c;
    sincosf((float)s * inv, &sn, &c);
    if ((b | kh) == 0) {
        g_cos[s * 32 + d] = c;
        g_sin[s * 32 + d] = sn;
    }

    size_t ioff = (size_t)(b * S_LEN + s) * KSTRIDE + kh * HDIM + d;
    size_t ooff = ((size_t)(b * KVHEADS + kh) * S_LEN + s) * HDIM + d;
    float x = K[ioff], y = K[ioff + 32];
    Khalf[ooff]      = __float2half(x * c - y * sn);
    Khalf[ooff + 32] = __float2half(y * c + x * sn);
    Vhalf[ooff]      = __float2half(V[ioff]);
    Vhalf[ooff + 32] = __float2half(V[ioff + 32]);
}

__device__ __forceinline__ unsigned smem_u32(const void* p) {
    return (unsigned)__cvta_generic_to_shared(p);
}
__device__ __forceinline__ void ldsm_x4(unsigned& r0, unsigned& r1, unsigned& r2, unsigned& r3, unsigned a) {
    asm volatile("ldmatrix.sync.aligned.m8n8.x4.shared.b16 {%0,%1,%2,%3}, [%4];"
                 : "=r"(r0), "=r"(r1), "=r"(r2), "=r"(r3) : "r"(a));
}
__device__ __forceinline__ void ldsm_x4_t(unsigned& r0, unsigned& r1, unsigned& r2, unsigned& r3, unsigned a) {
    asm volatile("ldmatrix.sync.aligned.m8n8.x4.trans.shared.b16 {%0,%1,%2,%3}, [%4];"
                 : "=r"(r0), "=r"(r1), "=r"(r2), "=r"(r3) : "r"(a));
}
// fp32-accum MMA (PV)
__device__ __forceinline__ void mma16816(float* c, const unsigned* a, unsigned b0, unsigned b1) {
    asm volatile("mma.sync.aligned.m16n8k16.row.col.f32.f16.f16.f32 "
                 "{%0,%1,%2,%3}, {%4,%5,%6,%7}, {%8,%9}, {%0,%1,%2,%3};"
                 : "+f"(c[0]), "+f"(c[1]), "+f"(c[2]), "+f"(c[3])
                 : "r"(a[0]), "r"(a[1]), "r"(a[2]), "r"(a[3]), "r"(b0), "r"(b1));
}
// fp16-accum MMA (QK^T): 2x rate, scores land packed fp16x2
__device__ __forceinline__ void mma16816_f16(unsigned* c, const unsigned* a, unsigned b0, unsigned b1) {
    asm volatile("mma.sync.aligned.m16n8k16.row.col.f16.f16.f16.f16 "
                 "{%0,%1}, {%2,%3,%4,%5}, {%6,%7}, {%0,%1};"
                 : "+r"(c[0]), "+r"(c[1])
                 : "r"(a[0]), "r"(a[1]), "r"(a[2]), "r"(a[3]), "r"(b0), "r"(b1));
}
__device__ __forceinline__ unsigned h2ex2(unsigned x) {
    unsigned d;
    asm("ex2.approx.f16x2 %0, %1;" : "=r"(d) : "r"(x));
    return d;
}
__device__ __forceinline__ unsigned hadd2u(unsigned a, unsigned b) {
    __half2 r = __hadd2(*reinterpret_cast<__half2*>(&a), *reinterpret_cast<__half2*>(&b));
    return *reinterpret_cast<unsigned*>(&r);
}
__device__ __forceinline__ void cp16(unsigned dst, const void* src) {
    asm volatile("cp.async.cg.shared.global [%0], [%1], 16;" :: "r"(dst), "l"(src));
}
__device__ __forceinline__ void cp_commit() {
    asm volatile("cp.async.commit_group;");
}
template<int N> __device__ __forceinline__ void cp_wait() {
    asm volatile("cp.async.wait_group %0;" :: "n"(N));
}

// fp16 -inf halves for additive masking (score + (-inf) -> -inf; ex2 -> 0)
#define NEGINF_LO 0x0000FC00u
#define NEGINF_HI 0xFC000000u

// CTA: 128 threads / 4 warps. Warp w = head kvh*4+w, owns ALL 32 queries
// (M=32, two m16 tiles); K/V B-fragments serve 2x MMAs each.
__global__ void __launch_bounds__(128, 3)
attn_kernel(const float* __restrict__ Q, float* __restrict__ O)
{
    extern __shared__ __align__(16) __half sm[];
    __half* qhbuf = sm;                    // transient Q staging (overlays stage 0)
    const unsigned kvsm = smem_u32(sm);

    const int tid  = threadIdx.x;
    const int w    = tid >> 5;
    const int lane = tid & 31;
    const int g    = lane >> 2;
    const int t    = lane & 3;
    const int qs   = blockIdx.x * QTILE;
    const int kvh  = blockIdx.y;
    const int b    = blockIdx.z;

    // RoPE Q: fp32 gmem -> fp16 smem (scaled by 0.125*log2e), 1 thread/row
    {
        const int row = tid;                 // head row>>5, query row&31
        const int qg  = qs + (row & 31);
        const float* qp = Q + ((size_t)(b * S_LEN + qg) * QSTRIDE
                               + (kvh * GROUP + (row >> 5)) * HDIM);
        float xv[64], cs[32], sn[32];
        #pragma unroll
        for (int i = 0; i < 16; ++i)
            *reinterpret_cast<float4*>(&xv[4 * i]) = reinterpret_cast<const float4*>(qp)[i];
        const float4* ct4 = reinterpret_cast<const float4*>(g_cos + qg * 32);
        const float4* st4 = reinterpret_cast<const float4*>(g_sin + qg * 32);
        #pragma unroll
        for (int i = 0; i < 8; ++i) {
            *reinterpret_cast<float4*>(&cs[4 * i]) = ct4[i];
            *reinterpret_cast<float4*>(&sn[4 * i]) = st4[i];
        }
        __half2* rowp = reinterpret_cast<__half2*>(qhbuf + row * KROW);
        float r[64];
        #pragma unroll
        for (int d = 0; d < 32; ++d) {
            r[d]      = (xv[d] * cs[d] - xv[d + 32] * sn[d]) * QSCALE;
            r[d + 32] = (xv[d + 32] * cs[d] + xv[d] * sn[d]) * QSCALE;
        }
        #pragma unroll
        for (int j = 0; j < 32; ++j)
            rowp[j] = __floats2half2_rn(r[2 * j], r[2 * j + 1]);
    }
    __syncthreads();

    // persistent Q fragments: 2 m16 tiles per warp
    unsigned qa[2][4][4];
    {
        unsigned qbase = smem_u32(qhbuf);
        int colh = (lane >> 4) * 8;
        #pragma unroll
        for (int mi = 0; mi < 2; ++mi) {
            int row = w * 32 + mi * 16 + (lane & 15);
            #pragma unroll
            for (int ki = 0; ki < 4; ++ki) {
                unsigned a = qbase + (unsigned)((row * KROW + ki * 16 + colh) * 2);
                ldsm_x4(qa[mi][ki][0], qa[mi][ki][1], qa[mi][ki][2], qa[mi][ki][3], a);
            }
        }
    }
    __syncthreads();   // Q read done; stage 0 may overwrite

    float of[2][8][4];
    #pragma unroll
    for (int mi = 0; mi < 2; ++mi)
        #pragma unroll
        for (int n = 0; n < 8; ++n)
            #pragma unroll
            for (int e = 0; e < 4; ++e) of[mi][n][e] = 0.f;
    float lsum[4] = {0.f, 0.f, 0.f, 0.f};

    const int j0  = (qs >= WIN) ? ((qs - WIN) & ~(NC - 1)) : 0;
    const int nch = (qs + QTILE - j0 + NC - 1) / NC;

    const __half* ksrc = Khalf + ((size_t)(b * KVHEADS + kvh) * S_LEN) * HDIM;
    const __half* vsrc = Vhalf + ((size_t)(b * KVHEADS + kvh) * S_LEN) * HDIM;

    const int kb_key = ((lane >> 4) & 1) * 8 + (lane & 7);
    const int kb_dim = ((lane >> 3) & 1) * 8;
    const int vb_key = ((lane >> 3) & 1) * 8 + (lane & 7);
    const int vb_dim = ((lane >> 4) & 1) * 8;

    auto stage_load = [&](int ci, int s) {
        int c0 = j0 + ci * NC;
        unsigned base = kvsm + (unsigned)(s * STAGE_HALVES * 2);
        #pragma unroll
        for (int it = 0; it < 8; ++it) {
            int idx = tid + it * 128;
            int tensor = idx >> 9;
            int r = (idx >> 3) & 63, p = idx & 7;
            const __half* src = (tensor ? vsrc : ksrc) + (size_t)(c0 + r) * HDIM + p * 8;
            unsigned dst = base + (unsigned)((tensor * NC * KROW + r * KROW + p * 8) * 2);
            cp16(dst, src);
        }
        cp_commit();
    };

    stage_load(0, 0);

    for (int ci = 0; ci < nch; ++ci) {
        if (ci + 1 < nch) { stage_load(ci + 1, (ci + 1) & 1); cp_wait<1>(); }
        else              { cp_wait<0>(); }
        __syncthreads();

        const unsigned ks = kvsm + (unsigned)(((ci & 1) * STAGE_HALVES) * 2);
        const unsigned vs = ks + (unsigned)(NC * KROW * 2);
        const int c0 = j0 + ci * NC;

        unsigned l2[4] = {0u, 0u, 0u, 0u};

        #pragma unroll
        for (int np = 0; np < 4; ++np) {
            const int colbase = c0 + np * 16;
            if (colbase > qs + 31 || colbase + 15 + WIN < qs) continue;

            unsigned kb[4][4];
            #pragma unroll
            for (int ki = 0; ki < 4; ++ki) {
                unsigned a = ks + (unsigned)((((np * 16 + kb_key) * KROW) + ki * 16 + kb_dim) * 2);
                ldsm_x4(kb[ki][0], kb[ki][1], kb[ki][2], kb[ki][3], a);
            }

            // QK^T in fp16 accum: sf16[mi][ni] = {row g pair, row g+8 pair}
            unsigned sf16[2][2][2];
            #pragma unroll
            for (int mi = 0; mi < 2; ++mi)
                #pragma unroll
                for (int ni = 0; ni < 2; ++ni)
                    sf16[mi][ni][0] = sf16[mi][ni][1] = 0u;
            #pragma unroll
            for (int ki = 0; ki < 4; ++ki) {
                mma16816_f16(sf16[0][0], qa[0][ki], kb[ki][0], kb[ki][1]);
                mma16816_f16(sf16[0][1], qa[0][ki], kb[ki][2], kb[ki][3]);
                mma16816_f16(sf16[1][0], qa[1][ki], kb[ki][0], kb[ki][1]);
                mma16816_f16(sf16[1][1], qa[1][ki], kb[ki][2], kb[ki][3]);
            }

            // hoist V fragments: LDS latency hides under exp XU chain
            unsigned vb[4][4];
            #pragma unroll
            for (int dp = 0; dp < 4; ++dp) {
                unsigned a = vs + (unsigned)((((np * 16 + vb_key) * KROW) + dp * 16 + vb_dim) * 2);
                ldsm_x4_t(vb[dp][0], vb[dp][1], vb[dp][2], vb[dp][3], a);
            }

            // mask (additive -inf in fp16) + exp (f16x2) + row sums
            unsigned pa[2][4];
            #pragma unroll
            for (int mi = 0; mi < 2; ++mi) {
                const int qg0 = qs + mi * 16 + g;
                const int qg1 = qg0 + 8;
                const bool full = (colbase + 15 <= qs + mi * 16) &&
                                  (colbase >= qs + mi * 16 + 15 - WIN);
                #pragma unroll
                for (int ni = 0; ni < 2; ++ni) {
                    unsigned c0r = sf16[mi][ni][0];
                    unsigned c1r = sf16[mi][ni][1];
                    if (!full) {
                        int p0 = colbase + ni * 8 + 2 * t;
                        int p1 = p0 + 1;
                        unsigned m0 = ((p0 <= qg0 && p0 + WIN >= qg0) ? 0u : NEGINF_LO)
                                    | ((p1 <= qg0 && p1 + WIN >= qg0) ? 0u : NEGINF_HI);
                        unsigned m1 = ((p0 <= qg1 && p0 + WIN >= qg1) ? 0u : NEGINF_LO)
                                    | ((p1 <= qg1 && p1 + WIN >= qg1) ? 0u : NEGINF_HI);
                        c0r = hadd2u(c0r, m0);
                        c1r = hadd2u(c1r, m1);
                    }
                    unsigned e0 = h2ex2(c0r);
                    unsigned e1 = h2ex2(c1r);
                    pa[mi][ni * 2 + 0] = e0;
                    pa[mi][ni * 2 + 1] = e1;
                    l2[mi * 2 + 0] = hadd2u(l2[mi * 2 + 0], e0);
                    l2[mi * 2 + 1] = hadd2u(l2[mi * 2 + 1], e1);
                }
            }

            #pragma unroll
            for (int dp = 0; dp < 4; ++dp) {
                mma16816(of[0][2 * dp],     pa[0], vb[dp][0], vb[dp][1]);
                mma16816(of[0][2 * dp + 1], pa[0], vb[dp][2], vb[dp][3]);
                mma16816(of[1][2 * dp],     pa[1], vb[dp][0], vb[dp][1]);
                mma16816(of[1][2 * dp + 1], pa[1], vb[dp][2], vb[dp][3]);
            }
        }

        #pragma unroll
        for (int i = 0; i < 4; ++i) {
            __half2 h = *reinterpret_cast<__half2*>(&l2[i]);
            lsum[i] += __low2float(h) + __high2float(h);
        }
        __syncthreads();
    }

    #pragma unroll
    for (int i = 0; i < 4; ++i) {
        float v = lsum[i];
        v += __shfl_xor_sync(0xffffffffu, v, 1);
        v += __shfl_xor_sync(0xffffffffu, v, 2);
        lsum[i] = 1.f / v;
    }
    const int head = kvh * GROUP + w;
    float* obase = O + (size_t)(b * S_LEN) * QSTRIDE + head * HDIM;
    #pragma unroll
    for (int mi = 0; mi < 2; ++mi) {
        const int r0 = qs + mi * 16 + g;
        const int r1 = r0 + 8;
        #pragma unroll
        for (int n = 0; n < 8; ++n) {
            int col = n * 8 + 2 * t;
            float2 v0 = make_float2(of[mi][n][0] * lsum[mi * 2],
                                    of[mi][n][1] * lsum[mi * 2]);
            float2 v1 = make_float2(of[mi][n][2] * lsum[mi * 2 + 1],
                                    of[mi][n][3] * lsum[mi * 2 + 1]);
            *reinterpret_cast<float2*>(obase + (size_t)r0 * QSTRIDE + col) = v0;
            *reinterpret_cast<float2*>(obase + (size_t)r1 * QSTRIDE + col) = v1;
        }
    }
}

extern "C" void kernel_launch(void* const* d_in, const int* in_sizes, int n_in,
                              void* d_out, int out_size) {
    const float* Q = (const float*)d_in[0];
    const float* K = (const float*)d_in[1];
    const float* V = (const float*)d_in[2];
    float* O = (float*)d_out;

    cudaFuncSetAttribute(attn_kernel, cudaFuncAttributeMaxDynamicSharedMemorySize, SMEM_BYTES);

    prep_kv_kernel<<<(BATCH * S_LEN * KVHEADS * 32 + 255) / 256, 256>>>(K, V);

    dim3 grid(S_LEN / QTILE, KVHEADS, BATCH);
    attn_kernel<<<grid, 128, SMEM_BYTES>>>(Q, O);
}